// round 5
// baseline (speedup 1.0000x reference)
#include <cuda_runtime.h>

#define NN 50000
#define EE 800000
#define HH 64
#define GG 256
#define OUTD 32

// ---------------- scratch (static __device__, no allocations) ----------------
__device__ __align__(16) int   g_deg[NN];
__device__ __align__(16) int   g_rowptr[NN + 1];
__device__ __align__(16) int   g_cursor[NN];
__device__ __align__(16) int   g_es[EE];            // src | (attr<<16)
__device__ __align__(16) float g_h[2][NN * HH];
__device__ __align__(16) float g_q[NN * HH];
__device__ __align__(16) float g_k[NN * HH];
__device__ __align__(16) float g_v[NN * HH];
__device__ __align__(16) float g_s[NN * HH];
__device__ __align__(16) float g_etab[3 * 10 * 64]; // per-layer 10x64 edge tables
__device__ __align__(16) float g_gate[NN];
__device__ __align__(16) float g_eg[NN];
__device__ __align__(16) float g_gmax[GG];
__device__ __align__(16) float g_gden[GG];

// ---------------- preprocessing ----------------
__global__ void k_zero_deg() {
    int i = blockIdx.x * blockDim.x + threadIdx.x;
    if (i < NN) g_deg[i] = 0;
}

__global__ void k_hist(const int* __restrict__ dst) {
    int i = blockIdx.x * blockDim.x + threadIdx.x;
    if (i < EE) atomicAdd(&g_deg[dst[i]], 1);
}

// single-block exclusive scan of g_deg -> g_rowptr / g_cursor
__global__ void k_scan() {
    __shared__ int wsum[32];
    __shared__ int s_carry;
    int tid = threadIdx.x, lane = tid & 31, wid = tid >> 5;
    if (tid == 0) s_carry = 0;
    __syncthreads();
    for (int base = 0; base < NN; base += 1024) {
        int i = base + tid;
        int v = (i < NN) ? g_deg[i] : 0;
        int x = v;
        #pragma unroll
        for (int off = 1; off < 32; off <<= 1) {
            int y = __shfl_up_sync(0xffffffffu, x, off);
            if (lane >= off) x += y;
        }
        if (lane == 31) wsum[wid] = x;
        __syncthreads();
        if (wid == 0) {
            int s = wsum[lane];
            #pragma unroll
            for (int off = 1; off < 32; off <<= 1) {
                int y = __shfl_up_sync(0xffffffffu, s, off);
                if (lane >= off) s += y;
            }
            wsum[lane] = s;
        }
        __syncthreads();
        int carry = s_carry;
        int excl = carry + (wid ? wsum[wid - 1] : 0) + x - v;
        if (i < NN) { g_rowptr[i] = excl; g_cursor[i] = excl; }
        __syncthreads();
        if (tid == 1023) s_carry = carry + wsum[31];
        __syncthreads();
    }
    if (tid == 0) g_rowptr[NN] = s_carry;
}

__global__ void k_scatter(const int* __restrict__ src, const int* __restrict__ dst,
                          const int* __restrict__ ea) {
    int i = blockIdx.x * blockDim.x + threadIdx.x;
    if (i < EE) {
        int p = atomicAdd(&g_cursor[dst[i]], 1);
        g_es[p] = src[i] | (ea[i] << 16);   // src < 65536, attr < 10
    }
}

// e_tab[l][a][c] = sum_d edge_emb[a][d] * We[l][d][c]   (only 10 attr categories!)
__global__ void k_etab(const float* __restrict__ eemb, const float* __restrict__ We) {
    int t = blockIdx.x * blockDim.x + threadIdx.x;
    if (t >= 3 * 10 * 64) return;
    int l = t / 640, r = t % 640, a = r / 64, c = r % 64;
    float s = 0.f;
    #pragma unroll
    for (int d = 0; d < 32; d++) s = fmaf(eemb[a * 32 + d], We[l * 2048 + d * 64 + c], s);
    g_etab[t] = s;
}

__global__ void k_inith(const int* __restrict__ x, const float* __restrict__ nemb) {
    int t = blockIdx.x * blockDim.x + threadIdx.x;
    if (t < NN * HH) g_h[0][t] = nemb[x[t >> 6] * HH + (t & 63)];
}

// ---------------- node matmuls: two 64x64 GEMMs per call ----------------
// 4 nodes per warp, weights + per-warp h tile in smem, float2 register tiling.
__global__ void __launch_bounds__(256) k_mm(const float* __restrict__ Wa,
                                            const float* __restrict__ Wb,
                                            const float* __restrict__ ba,
                                            const float* __restrict__ bb,
                                            int pin, int mode) {
    extern __shared__ float sm[];   // [0,4096) Wa  [4096,8192) Wb  [8192..] bias  [8320..] h tiles
    const float* hsrc = g_h[pin];
    float* outA = mode ? g_v : g_q;
    float* outB = mode ? g_s : g_k;

    for (int t = threadIdx.x; t < 4096; t += 256) { sm[t] = Wa[t]; sm[4096 + t] = Wb[t]; }
    if (threadIdx.x < 64) { sm[8192 + threadIdx.x] = ba[threadIdx.x]; sm[8256 + threadIdx.x] = bb[threadIdx.x]; }
    __syncthreads();

    int gw = (blockIdx.x * 256 + threadIdx.x) >> 5;
    int nbase = gw * 4;
    if (nbase >= NN) return;
    int lane = threadIdx.x & 31;
    float* sh = &sm[8320 + (threadIdx.x >> 5) * 256];

    #pragma unroll
    for (int nn = 0; nn < 4; nn++)
        *(float2*)&sh[nn * 64 + 2 * lane] = *(const float2*)&hsrc[(nbase + nn) * 64 + 2 * lane];
    __syncwarp();

    float2 accA[4], accB[4];
    #pragma unroll
    for (int nn = 0; nn < 4; nn++) { accA[nn] = make_float2(0.f, 0.f); accB[nn] = make_float2(0.f, 0.f); }

    #pragma unroll 4
    for (int kk = 0; kk < 64; kk += 2) {
        float2 wa0 = *(float2*)&sm[kk * 64 + 2 * lane];
        float2 wa1 = *(float2*)&sm[(kk + 1) * 64 + 2 * lane];
        float2 wb0 = *(float2*)&sm[4096 + kk * 64 + 2 * lane];
        float2 wb1 = *(float2*)&sm[4096 + (kk + 1) * 64 + 2 * lane];
        #pragma unroll
        for (int nn = 0; nn < 4; nn++) {
            float2 hp = *(float2*)&sh[nn * 64 + kk];
            accA[nn].x = fmaf(hp.x, wa0.x, accA[nn].x);
            accA[nn].x = fmaf(hp.y, wa1.x, accA[nn].x);
            accA[nn].y = fmaf(hp.x, wa0.y, accA[nn].y);
            accA[nn].y = fmaf(hp.y, wa1.y, accA[nn].y);
            accB[nn].x = fmaf(hp.x, wb0.x, accB[nn].x);
            accB[nn].x = fmaf(hp.y, wb1.x, accB[nn].x);
            accB[nn].y = fmaf(hp.x, wb0.y, accB[nn].y);
            accB[nn].y = fmaf(hp.y, wb1.y, accB[nn].y);
        }
    }
    float2 bav = *(float2*)&sm[8192 + 2 * lane];
    float2 bbv = *(float2*)&sm[8256 + 2 * lane];
    #pragma unroll
    for (int nn = 0; nn < 4; nn++) {
        float2 oa = make_float2(accA[nn].x + bav.x, accA[nn].y + bav.y);
        float2 ob = make_float2(accB[nn].x + bbv.x, accB[nn].y + bbv.y);
        *(float2*)&outA[(nbase + nn) * 64 + 2 * lane] = oa;
        *(float2*)&outB[(nbase + nn) * 64 + 2 * lane] = ob;
    }
}

// ---------------- fused attention: warp per dst, online softmax ----------------
__global__ void __launch_bounds__(256) k_attn(int l, int pin, int pout) {
    __shared__ __align__(16) float s_e[640];
    for (int t = threadIdx.x; t < 640; t += 256) s_e[t] = g_etab[l * 640 + t];
    __syncthreads();

    int node = (blockIdx.x * 256 + threadIdx.x) >> 5;
    if (node >= NN) return;
    int lane = threadIdx.x & 31;
    int beg = g_rowptr[node], end = g_rowptr[node + 1];

    float2 qv = *(const float2*)&g_q[node * 64 + 2 * lane];
    float2 acc = make_float2(0.f, 0.f);
    float m = -1e30f, d = 0.f;

    for (int j = beg; j < end; j++) {
        int pk = __ldg(&g_es[j]);
        int src = pk & 0xFFFF, attr = pk >> 16;
        float2 ej = *(float2*)&s_e[attr * 64 + 2 * lane];
        float2 kj = *(const float2*)&g_k[src * 64 + 2 * lane];
        float part = qv.x * (kj.x + ej.x) + qv.y * (kj.y + ej.y);
        part += __shfl_xor_sync(0xffffffffu, part, 16);
        part += __shfl_xor_sync(0xffffffffu, part, 8);
        part += __shfl_xor_sync(0xffffffffu, part, 4);
        part += __shfl_xor_sync(0xffffffffu, part, 2);
        part += __shfl_xor_sync(0xffffffffu, part, 1);
        float alpha = part * 0.125f;                 // 1/sqrt(64)
        float nm = fmaxf(m, alpha);
        float sc = __expf(m - nm);
        float w  = __expf(alpha - nm);
        float2 vj = *(const float2*)&g_v[src * 64 + 2 * lane];
        d = d * sc + w;
        acc.x = acc.x * sc + w * (vj.x + ej.x);
        acc.y = acc.y * sc + w * (vj.y + ej.y);
        m = nm;
    }
    float inv = (d > 0.f) ? (1.f / d) : 0.f;
    float2 sk = *(const float2*)&g_s[node * 64 + 2 * lane];
    float2 o;
    o.x = fmaxf(fmaf(acc.x, inv, sk.x), 0.f);
    o.y = fmaxf(fmaf(acc.y, inv, sk.y), 0.f);
    *(float2*)&g_h[pout][node * 64 + 2 * lane] = o;
}

// ---------------- readout ----------------
__global__ void k_zero_out(float* __restrict__ out) {
    int t = blockIdx.x * blockDim.x + threadIdx.x;
    if (t < GG * OUTD) out[t] = 0.f;
    if (t < GG) { g_gmax[t] = -1e30f; g_gden[t] = 0.f; }
}

__device__ __forceinline__ void atomicMaxF(float* addr, float val) {
    int old = __float_as_int(*addr);
    while (__int_as_float(old) < val) {
        int assumed = old;
        old = atomicCAS((int*)addr, assumed, __float_as_int(val));
        if (old == assumed) break;
    }
}

__global__ void __launch_bounds__(256) k_gate(const float* __restrict__ gw,
                                              const float* __restrict__ gb,
                                              const int* __restrict__ batch) {
    int node = (blockIdx.x * 256 + threadIdx.x) >> 5;
    if (node >= NN) return;
    int lane = threadIdx.x & 31;
    float2 hv = *(const float2*)&g_h[1][node * 64 + 2 * lane];
    float2 wv = *(const float2*)&gw[2 * lane];
    float part = hv.x * wv.x + hv.y * wv.y;
    part += __shfl_xor_sync(0xffffffffu, part, 16);
    part += __shfl_xor_sync(0xffffffffu, part, 8);
    part += __shfl_xor_sync(0xffffffffu, part, 4);
    part += __shfl_xor_sync(0xffffffffu, part, 2);
    part += __shfl_xor_sync(0xffffffffu, part, 1);
    if (lane == 0) {
        float gval = part + gb[0];
        g_gate[node] = gval;
        atomicMaxF(&g_gmax[batch[node]], gval);
    }
}

__global__ void k_expsum(const int* __restrict__ batch) {
    int t = blockIdx.x * blockDim.x + threadIdx.x;
    if (t < NN) {
        int b = batch[t];
        float e = __expf(g_gate[t] - g_gmax[b]);
        g_eg[t] = e;
        atomicAdd(&g_gden[b], e);
    }
}

__global__ void __launch_bounds__(256) k_final(const float* __restrict__ outW,
                                               const float* __restrict__ outb,
                                               const int* __restrict__ batch,
                                               float* __restrict__ out) {
    int node = (blockIdx.x * 256 + threadIdx.x) >> 5;
    if (node >= NN) return;
    int lane = threadIdx.x & 31;   // lane == output column (OUT = 32)
    const float* hrow = &g_h[1][node * 64];
    float acc = 0.f;
    #pragma unroll 8
    for (int kk = 0; kk < 64; kk++) acc = fmaf(hrow[kk], outW[kk * 32 + lane], acc);
    int b = batch[node];
    float g = g_eg[node] / g_gden[b];
    atomicAdd(&out[b * 32 + lane], g * (acc + outb[lane]));
}

// ---------------- launch ----------------
extern "C" void kernel_launch(void* const* d_in, const int* in_sizes, int n_in,
                              void* d_out, int out_size) {
    const int*   x     = (const int*)d_in[0];
    const int*   ei    = (const int*)d_in[1];
    const int*   ea    = (const int*)d_in[2];
    const int*   batch = (const int*)d_in[3];
    const float* nemb  = (const float*)d_in[4];
    const float* eemb  = (const float*)d_in[5];
    const float* Wq    = (const float*)d_in[6];
    const float* Wk    = (const float*)d_in[7];
    const float* Wv    = (const float*)d_in[8];
    const float* We    = (const float*)d_in[9];
    const float* Ws    = (const float*)d_in[10];
    const float* bq    = (const float*)d_in[11];
    const float* bk    = (const float*)d_in[12];
    const float* bv    = (const float*)d_in[13];
    const float* bs    = (const float*)d_in[14];
    const float* gw    = (const float*)d_in[15];
    const float* gb    = (const float*)d_in[16];
    const float* oW    = (const float*)d_in[17];
    const float* ob    = (const float*)d_in[18];
    float* out = (float*)d_out;

    const int* esrc = ei;
    const int* edst = ei + EE;

    // build CSR by dst + edge tables + initial h
    k_zero_deg<<<(NN + 255) / 256, 256>>>();
    k_hist<<<(EE + 255) / 256, 256>>>(edst);
    k_scan<<<1, 1024>>>();
    k_scatter<<<(EE + 255) / 256, 256>>>(esrc, edst, ea);
    k_etab<<<8, 256>>>(eemb, We);
    k_inith<<<(NN * HH + 255) / 256, 256>>>(x, nemb);

    const int smem = (8320 + 8 * 256) * 4;   // 41472 B < 48KB
    for (int l = 0; l < 3; l++) {
        int pin = l & 1, pout = 1 - pin;
        k_mm<<<1563, 256, smem>>>(Wq + l * 4096, Wk + l * 4096, bq + l * 64, bk + l * 64, pin, 0);
        k_mm<<<1563, 256, smem>>>(Wv + l * 4096, Ws + l * 4096, bv + l * 64, bs + l * 64, pin, 1);
        k_attn<<<(NN + 7) / 8, 256>>>(l, pin, pout);
    }

    // readout (final h lives in g_h[1] after 3 layers)
    k_zero_out<<<32, 256>>>(out);
    k_gate<<<(NN + 7) / 8, 256>>>(gw, gb, batch);
    k_expsum<<<(NN + 255) / 256, 256>>>(batch);
    k_final<<<(NN + 7) / 8, 256>>>(oW, ob, batch, out);
}

// round 7
// speedup vs baseline: 1.5044x; 1.5044x over previous
#include <cuda_runtime.h>

#define NN 50000
#define EE 800000
#define HH 64
#define GG 256
#define OUTD 32

typedef unsigned long long u64;

// ---------------- packed f32x2 helpers (sm_103a FFMA2 via PTX) ----------------
__device__ __forceinline__ u64 pk2(float x, float y) {
    u64 r; asm("mov.b64 %0, {%1, %2};" : "=l"(r) : "f"(x), "f"(y)); return r;
}
__device__ __forceinline__ float2 unpk2(u64 v) {
    float2 f; asm("mov.b64 {%0, %1}, %2;" : "=f"(f.x), "=f"(f.y) : "l"(v)); return f;
}
__device__ __forceinline__ u64 ffma2(u64 a, u64 b, u64 c) {
    u64 d; asm("fma.rn.f32x2 %0, %1, %2, %3;" : "=l"(d) : "l"(a), "l"(b), "l"(c)); return d;
}

// ---------------- scratch (static __device__, no allocations) ----------------
__device__ __align__(16) int   g_deg[NN];
__device__ __align__(16) int   g_rowptr[NN + 1];
__device__ __align__(16) int   g_cursor[NN];
__device__ __align__(16) int   g_bsum[64];
__device__ __align__(16) int   g_es[EE];            // src | (attr<<16)
__device__ __align__(16) float g_h[2][NN * HH];
__device__ __align__(16) float g_q[NN * HH];
__device__ __align__(16) float g_k[NN * HH];
__device__ __align__(16) float g_v[NN * HH];
__device__ __align__(16) float g_s[NN * HH];
__device__ __align__(16) float g_etab[3 * 10 * 64]; // per-layer 10x64 edge tables
__device__ __align__(16) float g_eg[NN];
__device__ __align__(16) float g_gden[GG];

// ---------------- preprocessing ----------------
__global__ void k_zero_deg() {
    int i = blockIdx.x * blockDim.x + threadIdx.x;
    if (i < NN) g_deg[i] = 0;
}

__global__ void k_hist(const int* __restrict__ dst) {
    int i = blockIdx.x * blockDim.x + threadIdx.x;
    if (i < EE) atomicAdd(&g_deg[dst[i]], 1);
}

// multi-block scan: local block scan -> scan of block sums -> add offsets
__global__ void k_scan1() {
    __shared__ int ws[32];
    int tid = threadIdx.x, lane = tid & 31, wid = tid >> 5;
    int i = blockIdx.x * 1024 + tid;
    int v = (i < NN) ? g_deg[i] : 0;
    int x = v;
    #pragma unroll
    for (int off = 1; off < 32; off <<= 1) {
        int y = __shfl_up_sync(0xffffffffu, x, off);
        if (lane >= off) x += y;
    }
    if (lane == 31) ws[wid] = x;
    __syncthreads();
    if (wid == 0) {
        int s = ws[lane];
        #pragma unroll
        for (int off = 1; off < 32; off <<= 1) {
            int y = __shfl_up_sync(0xffffffffu, s, off);
            if (lane >= off) s += y;
        }
        ws[lane] = s;
    }
    __syncthreads();
    int excl = (wid ? ws[wid - 1] : 0) + x - v;
    if (i < NN) g_rowptr[i] = excl;           // local exclusive for now
    if (tid == 0) g_bsum[blockIdx.x] = ws[31];
}

__global__ void k_scan2() {   // 1 block, 64 threads: scan 49 block sums
    __shared__ int ws[2];
    int tid = threadIdx.x, lane = tid & 31, wid = tid >> 5;
    int v = (tid < 49) ? g_bsum[tid] : 0;
    int x = v;
    #pragma unroll
    for (int off = 1; off < 32; off <<= 1) {
        int y = __shfl_up_sync(0xffffffffu, x, off);
        if (lane >= off) x += y;
    }
    if (lane == 31) ws[wid] = x;
    __syncthreads();
    int incl = x + (wid ? ws[0] : 0);
    g_bsum[tid] = incl - v;                   // exclusive
    if (tid == 63) g_rowptr[NN] = incl;       // total
}

__global__ void k_scan3() {
    int i = blockIdx.x * 1024 + threadIdx.x;
    if (i < NN) {
        int r = g_rowptr[i] + g_bsum[blockIdx.x];
        g_rowptr[i] = r;
        g_cursor[i] = r;
    }
}

__global__ void k_scatter(const int* __restrict__ src, const int* __restrict__ dst,
                          const int* __restrict__ ea) {
    int i = blockIdx.x * blockDim.x + threadIdx.x;
    if (i < EE) {
        int p = atomicAdd(&g_cursor[dst[i]], 1);
        g_es[p] = src[i] | (ea[i] << 16);   // src < 65536, attr < 10
    }
}

// e_tab[l][a][c] = sum_d edge_emb[a][d] * We[l][d][c]   (only 10 attr categories)
__global__ void k_etab(const float* __restrict__ eemb, const float* __restrict__ We) {
    int t = blockIdx.x * blockDim.x + threadIdx.x;
    if (t >= 3 * 10 * 64) return;
    int l = t / 640, r = t % 640, a = r / 64, c = r % 64;
    float s = 0.f;
    #pragma unroll
    for (int d = 0; d < 32; d++) s = fmaf(eemb[a * 32 + d], We[l * 2048 + d * 64 + c], s);
    g_etab[t] = s;
}

__global__ void k_inith(const int* __restrict__ x, const float* __restrict__ nemb) {
    int t = blockIdx.x * blockDim.x + threadIdx.x;
    if (t < NN * HH) g_h[0][t] = nemb[x[t >> 6] * HH + (t & 63)];
}

// ---------------- fused node matmuls: q,k,v,s in one pass, packed FFMA2 -------
// smem: W[4][4096] | bias[4][64] | h tiles 8 warps x 256
#define MM_SMEM ((16384 + 256 + 8 * 256) * 4)

__global__ void __launch_bounds__(256) k_mm4(const float* __restrict__ Wq,
                                             const float* __restrict__ Wk,
                                             const float* __restrict__ Wv,
                                             const float* __restrict__ Ws,
                                             const float* __restrict__ bq,
                                             const float* __restrict__ bk,
                                             const float* __restrict__ bv,
                                             const float* __restrict__ bs,
                                             int pin) {
    extern __shared__ float sm[];
    for (int t = threadIdx.x; t < 1024; t += 256) {
        ((float4*)sm)[t]        = ((const float4*)Wq)[t];
        ((float4*)sm)[1024 + t] = ((const float4*)Wk)[t];
        ((float4*)sm)[2048 + t] = ((const float4*)Wv)[t];
        ((float4*)sm)[3072 + t] = ((const float4*)Ws)[t];
    }
    if (threadIdx.x < 64) {
        sm[16384 + threadIdx.x]       = bq[threadIdx.x];
        sm[16384 + 64 + threadIdx.x]  = bk[threadIdx.x];
        sm[16384 + 128 + threadIdx.x] = bv[threadIdx.x];
        sm[16384 + 192 + threadIdx.x] = bs[threadIdx.x];
    }
    __syncthreads();

    int wid = threadIdx.x >> 5, lane = threadIdx.x & 31;
    float* sh = &sm[16640 + wid * 256];
    const float* hsrc = g_h[pin];
    int totWarps = gridDim.x * 8;

    u64 bia[4];
    #pragma unroll
    for (int m = 0; m < 4; m++) bia[m] = *(const u64*)&sm[16384 + m * 64 + 2 * lane];

    for (int g = blockIdx.x * 8 + wid; g < NN / 4; g += totWarps) {
        int nbase = g * 4;
        #pragma unroll
        for (int nn = 0; nn < 4; nn++)
            *(float2*)&sh[nn * 64 + 2 * lane] = *(const float2*)&hsrc[(nbase + nn) * 64 + 2 * lane];
        __syncwarp();

        u64 acc[4][4];   // [mat][node]
        #pragma unroll
        for (int m = 0; m < 4; m++)
            #pragma unroll
            for (int nn = 0; nn < 4; nn++) acc[m][nn] = bia[m];

        #pragma unroll 8
        for (int kk = 0; kk < 64; kk += 2) {
            u64 w0[4], w1[4];
            #pragma unroll
            for (int m = 0; m < 4; m++) {
                w0[m] = *(const u64*)&sm[m * 4096 + kk * 64 + 2 * lane];
                w1[m] = *(const u64*)&sm[m * 4096 + (kk + 1) * 64 + 2 * lane];
            }
            #pragma unroll
            for (int nn = 0; nn < 4; nn++) {
                float2 hp = *(const float2*)&sh[nn * 64 + kk];
                u64 h0 = pk2(hp.x, hp.x);
                u64 h1 = pk2(hp.y, hp.y);
                #pragma unroll
                for (int m = 0; m < 4; m++) {
                    acc[m][nn] = ffma2(h0, w0[m], acc[m][nn]);
                    acc[m][nn] = ffma2(h1, w1[m], acc[m][nn]);
                }
            }
        }
        #pragma unroll
        for (int nn = 0; nn < 4; nn++) {
            int off = (nbase + nn) * 64 + 2 * lane;
            *(u64*)&g_q[off] = acc[0][nn];
            *(u64*)&g_k[off] = acc[1][nn];
            *(u64*)&g_v[off] = acc[2][nn];
            *(u64*)&g_s[off] = acc[3][nn];
        }
        __syncwarp();
    }
}

// ---------------- fused attention: 2 dst per warp, no-max softmax -------------
__global__ void __launch_bounds__(256) k_attn(int l, int pout) {
    __shared__ __align__(16) float4 s_e4[160];      // 10 attrs x 16 float4
    for (int t = threadIdx.x; t < 160; t += 256)
        s_e4[t] = ((const float4*)(g_etab + l * 640))[t];
    __syncthreads();

    int lane = threadIdx.x & 31;
    int hl = lane & 15;
    int node = (blockIdx.x * 8 + (threadIdx.x >> 5)) * 2 + ((lane >> 4) & 1);

    int beg = 0, deg = 0;
    if (node < NN) { beg = g_rowptr[node]; deg = g_rowptr[node + 1] - beg; }
    int dmax = max(deg, __shfl_xor_sync(0xffffffffu, deg, 16));

    float4 qv = make_float4(0.f, 0.f, 0.f, 0.f);
    if (node < NN) qv = __ldg((const float4*)(g_q + node * 64 + hl * 4));

    u64 acc0 = 0, acc1 = 0;
    float dsum = 0.f, wsum = 0.f;

    // software pipeline: pk two deep, k/v one deep
    int pk_n = 0;
    if (0 < deg) pk_n = __ldg(&g_es[beg]);
    float4 kj_n = make_float4(0.f, 0.f, 0.f, 0.f);
    float4 vj_n = make_float4(0.f, 0.f, 0.f, 0.f);
    int attr_n = pk_n >> 16;
    {
        int s = pk_n & 0xFFFF;
        if (0 < deg) {
            kj_n = __ldg((const float4*)(g_k + s * 64 + hl * 4));
            vj_n = __ldg((const float4*)(g_v + s * 64 + hl * 4));
        }
    }
    int pk_nn = 0;
    if (1 < deg) pk_nn = __ldg(&g_es[beg + 1]);

    for (int t = 0; t < dmax; t++) {
        bool act = t < deg;
        float4 kj = kj_n, vj = vj_n;
        int attr = attr_n;

        // stage t+1 loads
        int pkx = pk_nn;
        attr_n = pkx >> 16;
        int sx = pkx & 0xFFFF;
        kj_n = make_float4(0.f, 0.f, 0.f, 0.f);
        vj_n = make_float4(0.f, 0.f, 0.f, 0.f);
        if (t + 1 < deg) {
            kj_n = __ldg((const float4*)(g_k + sx * 64 + hl * 4));
            vj_n = __ldg((const float4*)(g_v + sx * 64 + hl * 4));
        }
        pk_nn = 0;
        if (t + 2 < deg) pk_nn = __ldg(&g_es[beg + t + 2]);

        // current edge
        float4 ej = s_e4[attr * 16 + hl];
        float part = fmaf(kj.x + ej.x, qv.x,
                     fmaf(kj.y + ej.y, qv.y,
                     fmaf(kj.z + ej.z, qv.z, (kj.w + ej.w) * qv.w)));
        part += __shfl_xor_sync(0xffffffffu, part, 8);
        part += __shfl_xor_sync(0xffffffffu, part, 4);
        part += __shfl_xor_sync(0xffffffffu, part, 2);
        part += __shfl_xor_sync(0xffffffffu, part, 1);
        float w = act ? __expf(part * 0.125f) : 0.f;   // 1/sqrt(64); max-sub redundant
        dsum += w;
        u64 w2 = pk2(w, w);
        acc0 = ffma2(w2, pk2(vj.x, vj.y), acc0);
        acc1 = ffma2(w2, pk2(vj.z, vj.w), acc1);
        if (act && hl == attr) wsum += w;              // per-attr weight sums (attr<10)
    }

    // apply edge-table contribution once: acc += sum_a wsum_a * e[a]
    #pragma unroll
    for (int a = 0; a < 10; a++) {
        float wa = __shfl_sync(0xffffffffu, wsum, (lane & 16) | a);
        float4 ea = s_e4[a * 16 + hl];
        u64 wa2 = pk2(wa, wa);
        acc0 = ffma2(wa2, pk2(ea.x, ea.y), acc0);
        acc1 = ffma2(wa2, pk2(ea.z, ea.w), acc1);
    }

    if (node < NN) {
        float inv = (dsum > 0.f) ? (1.f / dsum) : 0.f;
        float2 a01 = unpk2(acc0), a23 = unpk2(acc1);
        float4 sk = __ldg((const float4*)(g_s + node * 64 + hl * 4));
        float4 o;
        o.x = fmaxf(fmaf(a01.x, inv, sk.x), 0.f);
        o.y = fmaxf(fmaf(a01.y, inv, sk.y), 0.f);
        o.z = fmaxf(fmaf(a23.x, inv, sk.z), 0.f);
        o.w = fmaxf(fmaf(a23.y, inv, sk.w), 0.f);
        *(float4*)(g_h[pout] + node * 64 + hl * 4) = o;
    }
}

// ---------------- readout ----------------
__global__ void k_zero_out(float* __restrict__ out) {
    int t = blockIdx.x * blockDim.x + threadIdx.x;
    if (t < GG * OUTD) out[t] = 0.f;
    if (t < GG) g_gden[t] = 0.f;
}

__global__ void __launch_bounds__(256) k_gate2(const float* __restrict__ gw,
                                               const float* __restrict__ gb,
                                               const int* __restrict__ batch) {
    int node = (blockIdx.x * 256 + threadIdx.x) >> 5;
    if (node >= NN) return;
    int lane = threadIdx.x & 31;
    float2 hv = *(const float2*)&g_h[1][node * 64 + 2 * lane];
    float2 wv = *(const float2*)&gw[2 * lane];
    float part = hv.x * wv.x + hv.y * wv.y;
    part += __shfl_xor_sync(0xffffffffu, part, 16);
    part += __shfl_xor_sync(0xffffffffu, part, 8);
    part += __shfl_xor_sync(0xffffffffu, part, 4);
    part += __shfl_xor_sync(0xffffffffu, part, 2);
    part += __shfl_xor_sync(0xffffffffu, part, 1);
    if (lane == 0) {
        float e = __expf(part + gb[0]);       // max-sub redundant (exact same math)
        g_eg[node] = e;
        atomicAdd(&g_gden[batch[node]], e);
    }
}

__global__ void __launch_bounds__(256) k_final(const float* __restrict__ outW,
                                               const float* __restrict__ outb,
                                               const int* __restrict__ batch,
                                               float* __restrict__ out) {
    int node = (blockIdx.x * 256 + threadIdx.x) >> 5;
    if (node >= NN) return;
    int lane = threadIdx.x & 31;   // lane == output column (OUT = 32)
    const float* hrow = &g_h[1][node * 64];
    float acc = 0.f;
    #pragma unroll 8
    for (int kk = 0; kk < 64; kk++) acc = fmaf(hrow[kk], outW[kk * 32 + lane], acc);
    int b = batch[node];
    float g = g_eg[node] / g_gden[b];
    atomicAdd(&out[b * 32 + lane], g * (acc + outb[lane]));
}

// ---------------- launch ----------------
extern "C" void kernel_launch(void* const* d_in, const int* in_sizes, int n_in,
                              void* d_out, int out_size) {
    const int*   x     = (const int*)d_in[0];
    const int*   ei    = (const int*)d_in[1];
    const int*   ea    = (const int*)d_in[2];
    const int*   batch = (const int*)d_in[3];
    const float* nemb  = (const float*)d_in[4];
    const float* eemb  = (const float*)d_in[5];
    const float* Wq    = (const float*)d_in[6];
    const float* Wk    = (const float*)d_in[7];
    const float* Wv    = (const float*)d_in[8];
    const float* We    = (const float*)d_in[9];
    const float* Ws    = (const float*)d_in[10];
    const float* bq    = (const float*)d_in[11];
    const float* bk    = (const float*)d_in[12];
    const float* bv    = (const float*)d_in[13];
    const float* bs    = (const float*)d_in[14];
    const float* gw    = (const float*)d_in[15];
    const float* gb    = (const float*)d_in[16];
    const float* oW    = (const float*)d_in[17];
    const float* ob    = (const float*)d_in[18];
    float* out = (float*)d_out;

    const int* esrc = ei;
    const int* edst = ei + EE;

    cudaFuncSetAttribute((const void*)k_mm4,
                         cudaFuncAttributeMaxDynamicSharedMemorySize, MM_SMEM);

    // build CSR by dst + edge tables + initial h
    k_zero_deg<<<(NN + 255) / 256, 256>>>();
    k_hist<<<(EE + 255) / 256, 256>>>(edst);
    k_scan1<<<49, 1024>>>();
    k_scan2<<<1, 64>>>();
    k_scan3<<<49, 1024>>>();
    k_scatter<<<(EE + 255) / 256, 256>>>(esrc, edst, ea);
    k_etab<<<8, 256>>>(eemb, We);
    k_inith<<<(NN * HH + 255) / 256, 256>>>(x, nemb);

    for (int l = 0; l < 3; l++) {
        int pin = l & 1, pout = 1 - pin;
        k_mm4<<<444, 256, MM_SMEM>>>(Wq + l * 4096, Wk + l * 4096, Wv + l * 4096, Ws + l * 4096,
                                     bq + l * 64, bk + l * 64, bv + l * 64, bs + l * 64, pin);
        k_attn<<<3125, 256>>>(l, pout);
    }

    // readout (final h lives in g_h[1] after 3 layers)
    k_zero_out<<<32, 256>>>(out);
    k_gate2<<<(NN + 7) / 8, 256>>>(gw, gb, batch);
    k_final<<<(NN + 7) / 8, 256>>>(oW, ob, batch, out);
}